// round 2
// baseline (speedup 1.0000x reference)
#include <cuda_runtime.h>

#define EMB 128
#define MAXNODES 100000
#define ETILE 32
#define OROWS 8

// Scratch (device globals: no allocations allowed in kernel_launch)
__device__ __align__(128) float g_Lp[MAXNODES * EMB];     // left_proj
__device__ __align__(128) float g_Rp[MAXNODES * EMB];     // right_proj
__device__ __align__(128) float g_conv[MAXNODES * EMB];   // scatter accumulator
__device__ int g_is64;

// ---- packed f32x2 helpers ---------------------------------------------------
__device__ __forceinline__ unsigned long long pk2(float lo, float hi) {
    unsigned long long r;
    asm("mov.b64 %0, {%1, %2};" : "=l"(r) : "f"(lo), "f"(hi));
    return r;
}
__device__ __forceinline__ float upk_sum(unsigned long long a) {
    float lo, hi;
    asm("mov.b64 {%0, %1}, %2;" : "=f"(lo), "=f"(hi) : "l"(a));
    return lo + hi;
}
#define FMA2(acc, a, b) \
    asm("fma.rn.f32x2 %0, %1, %2, %3;" : "=l"(acc) : "l"(a), "l"(b), "l"(acc))

__device__ __forceinline__ void red_add_v4(float* p, float4 v) {
    asm volatile("red.global.add.v4.f32 [%0], {%1, %2, %3, %4};"
                 :: "l"(p), "f"(v.x), "f"(v.y), "f"(v.z), "f"(v.w) : "memory");
}

// ---------------------------------------------------------------------------
// Detect whether edge_indices buffer is int64 or int32 (JAX x64-off pitfall).
// ---------------------------------------------------------------------------
__global__ void detect_idx_kernel(const long long* __restrict__ e, int n64_safe) {
    if (blockIdx.x == 0 && threadIdx.x == 0) {
        int m = n64_safe < 64 ? n64_safe : 64;
        int ok = 1;
        for (int i = 0; i < m; i++) {
            long long v = e[i];
            if (v < 0 || v >= (1LL << 31)) { ok = 0; break; }
        }
        g_is64 = ok;
    }
}

__global__ void zero_conv_kernel(int n4) {
    int i = blockIdx.x * blockDim.x + threadIdx.x;
    if (i < n4) ((float4*)g_conv)[i] = make_float4(0.f, 0.f, 0.f, 0.f);
}

// ---------------------------------------------------------------------------
// out[m, j] = sum_k A[m,k] * W[j,k] + b[j]      (A: [n_rows,128], W: [128,128])
// 128 threads, thread j owns output column j; 64 rows per block, 4 at a time.
// ---------------------------------------------------------------------------
__global__ __launch_bounds__(128) void proj_kernel(
    const float* __restrict__ A, const float* __restrict__ W,
    const float* __restrict__ b, float* __restrict__ out, int n_rows)
{
    __shared__ __align__(16) float As[4][EMB];
    const int j = threadIdx.x;
    const int row0 = blockIdx.x * 64;
    const float bj = b ? b[j] : 0.0f;
    const ulonglong2* __restrict__ W2 = (const ulonglong2*)(W + j * EMB);

    for (int rt = 0; rt < 64; rt += 4) {
        const int rbase = row0 + rt;
        const int rr = threadIdx.x >> 5;
        const int c4 = threadIdx.x & 31;
        float4 v = make_float4(0.f, 0.f, 0.f, 0.f);
        if (rbase + rr < n_rows)
            v = ((const float4*)(A + (size_t)(rbase + rr) * EMB))[c4];
        __syncthreads();
        ((float4*)As[rr])[c4] = v;
        __syncthreads();

        unsigned long long a0 = pk2(bj, 0.f), a1 = pk2(bj, 0.f);
        unsigned long long a2 = pk2(bj, 0.f), a3 = pk2(bj, 0.f);
#pragma unroll
        for (int k4 = 0; k4 < 32; k4++) {
            const ulonglong2 w = W2[k4];
            ulonglong2 x;
            x = ((const ulonglong2*)As[0])[k4];
            FMA2(a0, w.x, x.x); FMA2(a0, w.y, x.y);
            x = ((const ulonglong2*)As[1])[k4];
            FMA2(a1, w.x, x.x); FMA2(a1, w.y, x.y);
            x = ((const ulonglong2*)As[2])[k4];
            FMA2(a2, w.x, x.x); FMA2(a2, w.y, x.y);
            x = ((const ulonglong2*)As[3])[k4];
            FMA2(a3, w.x, x.x); FMA2(a3, w.y, x.y);
        }
        if (rbase + 0 < n_rows) out[(size_t)(rbase + 0) * EMB + j] = upk_sum(a0);
        if (rbase + 1 < n_rows) out[(size_t)(rbase + 1) * EMB + j] = upk_sum(a1);
        if (rbase + 2 < n_rows) out[(size_t)(rbase + 2) * EMB + j] = upk_sum(a2);
        if (rbase + 3 < n_rows) out[(size_t)(rbase + 3) * EMB + j] = upk_sum(a3);
    }
}

// ---------------------------------------------------------------------------
// Fused edge stage: joint = Lp[s] + Rp[d] + ef*w_edge; t = relu(joint*scale);
// msg = t @ W_final^T + b_final; red.v4 into g_conv[d].
// 128 threads per block, ETILE=32 edges per block.
// ---------------------------------------------------------------------------
__global__ __launch_bounds__(128) void edge_kernel(
    const void* __restrict__ eidx_raw, const float* __restrict__ ef,
    const float* __restrict__ wedge, const float* __restrict__ Wf,
    const float* __restrict__ bf, const float* __restrict__ scale_p,
    int n_edges)
{
    __shared__ __align__(16) float Ts[ETILE][EMB];
    __shared__ int Ss[ETILE];
    __shared__ int Dd[ETILE];
    __shared__ float Fs[ETILE];
    const int e0 = blockIdx.x * ETILE;
    const float scale = scale_p[0];
    const int tid = threadIdx.x;
    const int warp = tid >> 5, lane = tid & 31;
    const int is64 = g_is64;
    const long long* __restrict__ e64 = (const long long*)eidx_raw;
    const int* __restrict__ e32 = (const int*)eidx_raw;

    // Phase A: preload all indices + edge features (no dep chains later)
    if (tid < ETILE) {
        const int ge = e0 + tid;
        int s = 0;
        if (ge < n_edges) s = is64 ? (int)e64[ge] : e32[ge];
        Ss[tid] = s;
    } else if (tid < 2 * ETILE) {
        const int e = tid - ETILE;
        const int ge = e0 + e;
        int d = -1;
        if (ge < n_edges) d = is64 ? (int)e64[n_edges + ge] : e32[n_edges + ge];
        Dd[e] = d;
    } else if (tid < 3 * ETILE) {
        const int e = tid - 2 * ETILE;
        const int ge = e0 + e;
        Fs[e] = (ge < n_edges) ? ef[ge] : 0.f;
    }
    __syncthreads();

    // Phase B: gather + combine + relu into shared tile (independent loads)
    const float4 we = ((const float4*)wedge)[lane];
#pragma unroll
    for (int e = warp; e < ETILE; e += 4) {
        float4 t = make_float4(0.f, 0.f, 0.f, 0.f);
        const int d = Dd[e];
        if (d >= 0) {
            const int s = Ss[e];
            const float4 l = ((const float4*)(g_Lp + (size_t)s * EMB))[lane];
            const float4 r = ((const float4*)(g_Rp + (size_t)d * EMB))[lane];
            const float fe = Fs[e];
            t.x = fmaxf(fmaf(fe, we.x, l.x + r.x) * scale, 0.f);
            t.y = fmaxf(fmaf(fe, we.y, l.y + r.y) * scale, 0.f);
            t.z = fmaxf(fmaf(fe, we.z, l.z + r.z) * scale, 0.f);
            t.w = fmaxf(fmaf(fe, we.w, l.w + r.w) * scale, 0.f);
        }
        ((float4*)Ts[e])[lane] = t;
    }
    __syncthreads();

    // Phase C: GEMM — thread j computes msg[e][j] for all 32 edges (f32x2)
    unsigned long long acc[ETILE];
    const float bj = bf[tid];
#pragma unroll
    for (int e = 0; e < ETILE; e++) acc[e] = pk2(bj, 0.f);
    const ulonglong2* __restrict__ Wrow = (const ulonglong2*)(Wf + (size_t)tid * EMB);
#pragma unroll 2
    for (int k4 = 0; k4 < 32; k4++) {
        const ulonglong2 w = Wrow[k4];
#pragma unroll
        for (int e = 0; e < ETILE; e++) {
            const ulonglong2 x = ((const ulonglong2*)Ts[e])[k4];  // broadcast LDS
            FMA2(acc[e], w.x, x.x);
            FMA2(acc[e], w.y, x.y);
        }
    }

    // Phase D: transpose through smem, then vectorized scatter (red.v4)
    __syncthreads();
#pragma unroll
    for (int e = 0; e < ETILE; e++) Ts[e][tid] = upk_sum(acc[e]);
    __syncthreads();

#pragma unroll
    for (int i = 0; i < 8; i++) {
        const int e = warp * 8 + i;
        const int d = Dd[e];
        if (d >= 0) {
            const float4 m = ((const float4*)Ts[e])[lane];
            red_add_v4(&g_conv[(size_t)d * EMB + lane * 4], m);
        }
    }
}

// ---------------------------------------------------------------------------
// Output MLP: h = [conv*scale_post ; right];  u = relu(h@W1^T + b1);
// out = u@W2^T + b2.  128 threads, OROWS rows per block.
// ---------------------------------------------------------------------------
__global__ __launch_bounds__(128) void out_kernel(
    const float* __restrict__ right, const float* __restrict__ scale_post_p,
    const float* __restrict__ W1, const float* __restrict__ b1,
    const float* __restrict__ W2, const float* __restrict__ b2,
    float* __restrict__ out, int n_right)
{
    __shared__ __align__(16) float Hs[OROWS][2 * EMB];
    __shared__ __align__(16) float Us[OROWS][EMB];
    const int j = threadIdx.x;
    const int row0 = blockIdx.x * OROWS;
    const float sp = scale_post_p[0];

    for (int i = threadIdx.x; i < OROWS * 64; i += 128) {
        const int r = i >> 6;
        const int c4 = i & 63;
        const int row = row0 + r;
        float4 v = make_float4(0.f, 0.f, 0.f, 0.f);
        if (row < n_right) {
            if (c4 < 32) {
                v = ((const float4*)(g_conv + (size_t)row * EMB))[c4];
                v.x *= sp; v.y *= sp; v.z *= sp; v.w *= sp;
            } else {
                v = ((const float4*)(right + (size_t)row * EMB))[c4 - 32];
            }
        }
        ((float4*)Hs[r])[c4] = v;
    }
    __syncthreads();

    unsigned long long acc[OROWS];
    const float b1j = b1[j];
#pragma unroll
    for (int r = 0; r < OROWS; r++) acc[r] = pk2(b1j, 0.f);
    const ulonglong2* __restrict__ W1r = (const ulonglong2*)(W1 + (size_t)j * 2 * EMB);
#pragma unroll 2
    for (int k4 = 0; k4 < 64; k4++) {
        const ulonglong2 w = W1r[k4];
#pragma unroll
        for (int r = 0; r < OROWS; r++) {
            const ulonglong2 x = ((const ulonglong2*)Hs[r])[k4];
            FMA2(acc[r], w.x, x.x);
            FMA2(acc[r], w.y, x.y);
        }
    }
#pragma unroll
    for (int r = 0; r < OROWS; r++) Us[r][j] = fmaxf(upk_sum(acc[r]), 0.f);
    __syncthreads();

    unsigned long long acc2[OROWS];
    const float b2j = b2[j];
#pragma unroll
    for (int r = 0; r < OROWS; r++) acc2[r] = pk2(b2j, 0.f);
    const ulonglong2* __restrict__ W2r = (const ulonglong2*)(W2 + (size_t)j * EMB);
#pragma unroll 2
    for (int k4 = 0; k4 < 32; k4++) {
        const ulonglong2 w = W2r[k4];
#pragma unroll
        for (int r = 0; r < OROWS; r++) {
            const ulonglong2 x = ((const ulonglong2*)Us[r])[k4];
            FMA2(acc2[r], w.x, x.x);
            FMA2(acc2[r], w.y, x.y);
        }
    }
#pragma unroll
    for (int r = 0; r < OROWS; r++) {
        const int row = row0 + r;
        if (row < n_right) out[(size_t)row * EMB + j] = upk_sum(acc2[r]);
    }
}

// ---------------------------------------------------------------------------
extern "C" void kernel_launch(void* const* d_in, const int* in_sizes, int n_in,
                              void* d_out, int out_size)
{
    const float* left   = (const float*)d_in[0];
    const void*  eidx   = d_in[1];
    const float* ef     = (const float*)d_in[2];
    const float* right  = (const float*)d_in[3];
    // d_in[4] = scatter_out_size scalar (derived from right_features instead)
    const float* W_left      = (const float*)d_in[5];
    const float* b_left      = (const float*)d_in[6];
    const float* W_edge      = (const float*)d_in[7];
    const float* W_right     = (const float*)d_in[8];
    const float* scale_final = (const float*)d_in[9];
    const float* W_final     = (const float*)d_in[10];
    const float* b_final     = (const float*)d_in[11];
    const float* scale_post  = (const float*)d_in[12];
    const float* W_out1      = (const float*)d_in[13];
    const float* b_out1      = (const float*)d_in[14];
    const float* W_out2      = (const float*)d_in[15];
    const float* b_out2      = (const float*)d_in[16];

    const int n_left  = in_sizes[0] / EMB;
    const int n_edges = in_sizes[2];          // edge_features count (EDGE_FEAT=1)
    const int n_right = in_sizes[3] / EMB;

    float *Lp, *Rp;
    cudaGetSymbolAddress((void**)&Lp, g_Lp);
    cudaGetSymbolAddress((void**)&Rp, g_Rp);

    detect_idx_kernel<<<1, 32>>>((const long long*)eidx, n_edges);

    proj_kernel<<<(n_left + 63) / 64, 128>>>(left, W_left, b_left, Lp, n_left);
    proj_kernel<<<(n_right + 63) / 64, 128>>>(right, W_right, nullptr, Rp, n_right);

    const int n4 = n_right * EMB / 4;
    zero_conv_kernel<<<(n4 + 255) / 256, 256>>>(n4);

    edge_kernel<<<(n_edges + ETILE - 1) / ETILE, 128>>>(
        eidx, ef, W_edge, W_final, b_final, scale_final, n_edges);

    out_kernel<<<(n_right + OROWS - 1) / OROWS, 128>>>(
        right, scale_post, W_out1, b_out1, W_out2, b_out2,
        (float*)d_out, n_right);
}

// round 3
// speedup vs baseline: 1.9951x; 1.9951x over previous
#include <cuda_runtime.h>

#define EMB 128
#define ETILE 64
#define OROWS 16
#define PROWS 8
#define MAXNODES 100000

// Scratch (device globals: no allocations allowed in kernel_launch)
__device__ __align__(128) float g_Lp[MAXNODES * EMB];
__device__ __align__(128) float g_Rp[MAXNODES * EMB];
__device__ __align__(128) float g_conv[MAXNODES * EMB];
__device__ __align__(128) float g_WLT[EMB * EMB];      // W_left^T
__device__ __align__(128) float g_WRT[EMB * EMB];      // W_right^T
__device__ __align__(128) float g_WfT[EMB * EMB];      // W_final^T
__device__ __align__(128) float g_W1T[2 * EMB * EMB];  // W_out1^T
__device__ __align__(128) float g_W2T[EMB * EMB];      // W_out2^T
__device__ int g_is64;

__device__ __forceinline__ void red_add_v4(float* p, float4 v) {
    asm volatile("red.global.add.v4.f32 [%0], {%1, %2, %3, %4};"
                 :: "l"(p), "f"(v.x), "f"(v.y), "f"(v.z), "f"(v.w) : "memory");
}

// ---------------------------------------------------------------------------
// Detect whether edge_indices buffer is int64 or int32 (JAX x64-off pitfall).
// ---------------------------------------------------------------------------
__global__ void detect_idx_kernel(const long long* __restrict__ e, int n64_safe) {
    if (blockIdx.x == 0 && threadIdx.x == 0) {
        int m = n64_safe < 64 ? n64_safe : 64;
        int ok = 1;
        for (int i = 0; i < m; i++) {
            long long v = e[i];
            if (v < 0 || v >= (1LL << 31)) { ok = 0; break; }
        }
        g_is64 = ok;
    }
}

// ---------------------------------------------------------------------------
// prep: zero g_conv + transpose all weight matrices (coalesced writes).
// ---------------------------------------------------------------------------
__global__ void prep_kernel(const float* __restrict__ Wl, const float* __restrict__ Wr,
                            const float* __restrict__ Wf, const float* __restrict__ W1,
                            const float* __restrict__ W2, int n4) {
    const int idx = blockIdx.x * blockDim.x + threadIdx.x;
    if (idx < n4) ((float4*)g_conv)[idx] = make_float4(0.f, 0.f, 0.f, 0.f);
    if (idx < EMB * EMB) {
        const int k = idx >> 7, j = idx & 127;
        g_WLT[idx] = Wl[j * EMB + k];
        g_WRT[idx] = Wr[j * EMB + k];
        g_WfT[idx] = Wf[j * EMB + k];
        g_W2T[idx] = W2[j * EMB + k];
    }
    if (idx < 2 * EMB * EMB) {
        const int k = idx >> 7, j = idx & 127;
        g_W1T[idx] = W1[j * 2 * EMB + k];  // W1: [128][256] -> W1T: [256][128]
    }
}

// ---------------------------------------------------------------------------
// Merged projections: out[m,j] = sum_k A[m,k] * WT[k,j] (+ b[j] for left side)
// Thread j owns column j; WT loads are warp-coalesced.
// ---------------------------------------------------------------------------
__global__ __launch_bounds__(128) void proj_kernel(
    const float* __restrict__ left, const float* __restrict__ right,
    const float* __restrict__ bL, int n_left, int n_right, int blocksL)
{
    __shared__ __align__(16) float As[PROWS][EMB];
    const int j = threadIdx.x;

    const float* __restrict__ A;
    const float* __restrict__ WT;
    float* out; int n; float bj; int row0;
    if (blockIdx.x < blocksL) {
        A = left; WT = g_WLT; out = g_Lp; n = n_left;
        bj = bL[j]; row0 = blockIdx.x * 64;
    } else {
        A = right; WT = g_WRT; out = g_Rp; n = n_right;
        bj = 0.f; row0 = (blockIdx.x - blocksL) * 64;
    }

    for (int rt = 0; rt < 64; rt += PROWS) {
        const int rbase = row0 + rt;
        __syncthreads();
        for (int i = threadIdx.x; i < PROWS * 32; i += 128) {
            const int r = i >> 5, c4 = i & 31;
            float4 v = make_float4(0.f, 0.f, 0.f, 0.f);
            if (rbase + r < n)
                v = ((const float4*)(A + (size_t)(rbase + r) * EMB))[c4];
            ((float4*)As[r])[c4] = v;
        }
        __syncthreads();

        float acc[PROWS];
#pragma unroll
        for (int r = 0; r < PROWS; r++) acc[r] = bj;

#pragma unroll 2
        for (int k4 = 0; k4 < 32; k4++) {
            const float* __restrict__ wp = WT + (size_t)(k4 * 4) * EMB + j;
            const float w0 = wp[0];
            const float w1 = wp[EMB];
            const float w2 = wp[2 * EMB];
            const float w3 = wp[3 * EMB];
#pragma unroll
            for (int r = 0; r < PROWS; r++) {
                const float4 x = ((const float4*)As[r])[k4];
                acc[r] = fmaf(w0, x.x, acc[r]);
                acc[r] = fmaf(w1, x.y, acc[r]);
                acc[r] = fmaf(w2, x.z, acc[r]);
                acc[r] = fmaf(w3, x.w, acc[r]);
            }
        }
#pragma unroll
        for (int r = 0; r < PROWS; r++)
            if (rbase + r < n) out[(size_t)(rbase + r) * EMB + j] = acc[r];
    }
}

// ---------------------------------------------------------------------------
// Fused edge stage: joint = Lp[s] + Rp[d] + ef*w_edge; t = relu(joint*scale);
// msg = t @ Wf^T + b_final; red.v4 scatter into g_conv[d].
// 128 threads, ETILE=64 edges per block, W_final^T coalesced from L1.
// ---------------------------------------------------------------------------
__global__ __launch_bounds__(128) void edge_kernel(
    const void* __restrict__ eidx_raw, const float* __restrict__ ef,
    const float* __restrict__ wedge, const float* __restrict__ bf,
    const float* __restrict__ scale_p, int n_edges)
{
    __shared__ __align__(16) float Ts[ETILE][EMB];
    __shared__ int Ss[ETILE];
    __shared__ int Dd[ETILE];
    __shared__ float Fs[ETILE];
    const int e0 = blockIdx.x * ETILE;
    const float scale = scale_p[0];
    const int tid = threadIdx.x;
    const int warp = tid >> 5, lane = tid & 31;
    const int is64 = g_is64;
    const long long* __restrict__ e64 = (const long long*)eidx_raw;
    const int* __restrict__ e32 = (const int*)eidx_raw;

    // Phase A: preload indices + edge features
    if (tid < ETILE) {
        const int ge = e0 + tid;
        int s = 0, d = -1; float f = 0.f;
        if (ge < n_edges) {
            if (is64) { s = (int)e64[ge]; d = (int)e64[n_edges + ge]; }
            else      { s = e32[ge];      d = e32[n_edges + ge]; }
            f = ef[ge];
        }
        Ss[tid] = s; Dd[tid] = d; Fs[tid] = f;
    }
    __syncthreads();

    // Phase B: gather + combine + relu into shared tile
    const float4 we = ((const float4*)wedge)[lane];
    for (int e = warp; e < ETILE; e += 4) {
        float4 t = make_float4(0.f, 0.f, 0.f, 0.f);
        const int d = Dd[e];
        if (d >= 0) {
            const int s = Ss[e];
            const float4 l = ((const float4*)(g_Lp + (size_t)s * EMB))[lane];
            const float4 r = ((const float4*)(g_Rp + (size_t)d * EMB))[lane];
            const float fe = Fs[e];
            t.x = fmaxf(fmaf(fe, we.x, l.x + r.x) * scale, 0.f);
            t.y = fmaxf(fmaf(fe, we.y, l.y + r.y) * scale, 0.f);
            t.z = fmaxf(fmaf(fe, we.z, l.z + r.z) * scale, 0.f);
            t.w = fmaxf(fmaf(fe, we.w, l.w + r.w) * scale, 0.f);
        }
        ((float4*)Ts[e])[lane] = t;
    }
    __syncthreads();

    // Phase C: GEMM — thread j computes msg[e][j] for all 64 edges
    float acc[ETILE];
    const float bj = bf[tid];
#pragma unroll
    for (int e = 0; e < ETILE; e++) acc[e] = bj;

#pragma unroll 1
    for (int k4 = 0; k4 < 32; k4++) {
        const float* __restrict__ wp = g_WfT + (size_t)(k4 * 4) * EMB + tid;
        const float w0 = wp[0];
        const float w1 = wp[EMB];
        const float w2 = wp[2 * EMB];
        const float w3 = wp[3 * EMB];
#pragma unroll
        for (int e = 0; e < ETILE; e++) {
            const float4 x = ((const float4*)Ts[e])[k4];  // broadcast LDS
            acc[e] = fmaf(w0, x.x, acc[e]);
            acc[e] = fmaf(w1, x.y, acc[e]);
            acc[e] = fmaf(w2, x.z, acc[e]);
            acc[e] = fmaf(w3, x.w, acc[e]);
        }
    }

    // Phase D: transpose through smem, then vectorized scatter (red.v4)
    __syncthreads();
#pragma unroll
    for (int e = 0; e < ETILE; e++) Ts[e][tid] = acc[e];
    __syncthreads();

#pragma unroll 4
    for (int i = 0; i < ETILE / 4; i++) {
        const int e = warp * (ETILE / 4) + i;
        const int d = Dd[e];
        if (d >= 0) {
            const float4 m = ((const float4*)Ts[e])[lane];
            red_add_v4(&g_conv[(size_t)d * EMB + lane * 4], m);
        }
    }
}

// ---------------------------------------------------------------------------
// Output MLP: h = [conv*scale_post ; right];  u = relu(h@W1^T + b1);
// out = u@W2^T + b2.  128 threads, OROWS rows per block, coalesced W^T loads.
// ---------------------------------------------------------------------------
__global__ __launch_bounds__(128) void out_kernel(
    const float* __restrict__ right, const float* __restrict__ scale_post_p,
    const float* __restrict__ b1, const float* __restrict__ b2,
    float* __restrict__ out, int n_right)
{
    __shared__ __align__(16) float Hs[OROWS][2 * EMB];
    __shared__ __align__(16) float Us[OROWS][EMB];
    const int j = threadIdx.x;
    const int row0 = blockIdx.x * OROWS;
    const float sp = scale_post_p[0];

    for (int i = threadIdx.x; i < OROWS * 64; i += 128) {
        const int r = i >> 6;
        const int c4 = i & 63;
        const int row = row0 + r;
        float4 v = make_float4(0.f, 0.f, 0.f, 0.f);
        if (row < n_right) {
            if (c4 < 32) {
                v = ((const float4*)(g_conv + (size_t)row * EMB))[c4];
                v.x *= sp; v.y *= sp; v.z *= sp; v.w *= sp;
            } else {
                v = ((const float4*)(right + (size_t)row * EMB))[c4 - 32];
            }
        }
        ((float4*)Hs[r])[c4] = v;
    }
    __syncthreads();

    float acc[OROWS];
    const float b1j = b1[j];
#pragma unroll
    for (int r = 0; r < OROWS; r++) acc[r] = b1j;
#pragma unroll 1
    for (int k4 = 0; k4 < 64; k4++) {
        const float* __restrict__ wp = g_W1T + (size_t)(k4 * 4) * EMB + j;
        const float w0 = wp[0];
        const float w1 = wp[EMB];
        const float w2 = wp[2 * EMB];
        const float w3 = wp[3 * EMB];
#pragma unroll
        for (int r = 0; r < OROWS; r++) {
            const float4 x = ((const float4*)Hs[r])[k4];
            acc[r] = fmaf(w0, x.x, acc[r]);
            acc[r] = fmaf(w1, x.y, acc[r]);
            acc[r] = fmaf(w2, x.z, acc[r]);
            acc[r] = fmaf(w3, x.w, acc[r]);
        }
    }
#pragma unroll
    for (int r = 0; r < OROWS; r++) Us[r][j] = fmaxf(acc[r], 0.f);
    __syncthreads();

    float acc2[OROWS];
    const float b2j = b2[j];
#pragma unroll
    for (int r = 0; r < OROWS; r++) acc2[r] = b2j;
#pragma unroll 1
    for (int k4 = 0; k4 < 32; k4++) {
        const float* __restrict__ wp = g_W2T + (size_t)(k4 * 4) * EMB + j;
        const float w0 = wp[0];
        const float w1 = wp[EMB];
        const float w2 = wp[2 * EMB];
        const float w3 = wp[3 * EMB];
#pragma unroll
        for (int r = 0; r < OROWS; r++) {
            const float4 x = ((const float4*)Us[r])[k4];
            acc2[r] = fmaf(w0, x.x, acc2[r]);
            acc2[r] = fmaf(w1, x.y, acc2[r]);
            acc2[r] = fmaf(w2, x.z, acc2[r]);
            acc2[r] = fmaf(w3, x.w, acc2[r]);
        }
    }
#pragma unroll
    for (int r = 0; r < OROWS; r++) {
        const int row = row0 + r;
        if (row < n_right) out[(size_t)row * EMB + j] = acc2[r];
    }
}

// ---------------------------------------------------------------------------
extern "C" void kernel_launch(void* const* d_in, const int* in_sizes, int n_in,
                              void* d_out, int out_size)
{
    const float* left   = (const float*)d_in[0];
    const void*  eidx   = d_in[1];
    const float* ef     = (const float*)d_in[2];
    const float* right  = (const float*)d_in[3];
    // d_in[4] = scatter_out_size scalar (derived from right_features instead)
    const float* W_left      = (const float*)d_in[5];
    const float* b_left      = (const float*)d_in[6];
    const float* W_edge      = (const float*)d_in[7];
    const float* W_right     = (const float*)d_in[8];
    const float* scale_final = (const float*)d_in[9];
    const float* W_final     = (const float*)d_in[10];
    const float* b_final     = (const float*)d_in[11];
    const float* scale_post  = (const float*)d_in[12];
    const float* W_out1      = (const float*)d_in[13];
    const float* b_out1      = (const float*)d_in[14];
    const float* W_out2      = (const float*)d_in[15];
    const float* b_out2      = (const float*)d_in[16];

    const int n_left  = in_sizes[0] / EMB;
    const int n_edges = in_sizes[2];          // edge_features count (EDGE_FEAT=1)
    const int n_right = in_sizes[3] / EMB;

    // launch 0: index-width detection
    detect_idx_kernel<<<1, 32>>>((const long long*)eidx, n_edges);

    // launch 1: zero conv + transpose weights
    const int n4 = n_right * EMB / 4;
    const int prep_blocks = (n4 + 255) / 256;
    prep_kernel<<<prep_blocks, 256>>>(W_left, W_right, W_final, W_out1, W_out2, n4);

    // launch 2: merged projections
    const int blocksL = (n_left + 63) / 64;
    const int blocksR = (n_right + 63) / 64;
    proj_kernel<<<blocksL + blocksR, 128>>>(left, right, b_left, n_left, n_right, blocksL);

    // launch 3: fused edge stage (gather -> GEMM -> scatter)
    edge_kernel<<<(n_edges + ETILE - 1) / ETILE, 128>>>(
        eidx, ef, W_edge, b_final, scale_final, n_edges);

    // launch 4: output MLP
    out_kernel<<<(n_right + OROWS - 1) / OROWS, 128>>>(
        right, scale_post, b_out1, b_out2, (float*)d_out, n_right);
}